// round 4
// baseline (speedup 1.0000x reference)
#include <cuda_runtime.h>
#include <cuda_bf16.h>
#include <cstdint>

// Cross-stitch: per-channel 2x2 mix.
//   out_a[n,c,h,w] = w[c,0,0]*x_a + w[c,0,1]*x_b
//   out_b[n,c,h,w] = w[c,1,0]*x_a + w[c,1,1]*x_b
// Shapes: x_a, x_b: [32, 256, 64, 64] fp32. weights: [256, 2, 2] fp32.
// Output: out_a followed by out_b.
//
// HBM-bound at the 537MB traffic floor (~6.5TB/s achieved). 256-bit global
// accesses; reads via the non-coherent (.nc) read-only path with evict-first
// (.cs), writes evict-first.

static constexpr int C_ = 256;
static constexpr long long TOT  = 32LL * 256 * 64 * 64;   // 33,554,432 floats
static constexpr long long TOT8 = TOT / 8;                // 4,194,304 float8

__device__ __forceinline__ void ldg256_nc_cs(const float* __restrict__ p, float r[8]) {
    asm volatile("ld.global.nc.cs.v8.f32 {%0,%1,%2,%3,%4,%5,%6,%7}, [%8];"
                 : "=f"(r[0]), "=f"(r[1]), "=f"(r[2]), "=f"(r[3]),
                   "=f"(r[4]), "=f"(r[5]), "=f"(r[6]), "=f"(r[7])
                 : "l"(p));
}

__device__ __forceinline__ void stg256_cs(float* __restrict__ p, const float r[8]) {
    asm volatile("st.global.cs.v8.f32 [%0], {%1,%2,%3,%4,%5,%6,%7,%8};"
                 :: "l"(p),
                    "f"(r[0]), "f"(r[1]), "f"(r[2]), "f"(r[3]),
                    "f"(r[4]), "f"(r[5]), "f"(r[6]), "f"(r[7])
                 : "memory");
}

__global__ __launch_bounds__(256)
void cross_stitch_kernel(const float* __restrict__ xa,
                         const float* __restrict__ xb,
                         const float* __restrict__ w,   // [C,2,2]
                         float* __restrict__ oa,
                         float* __restrict__ ob)
{
    long long i8 = (long long)blockIdx.x * blockDim.x + threadIdx.x;  // float8 index
    long long off = i8 * 8;                                           // float offset

    // channel: float_index / 4096 mod 256 = (i8 >> 9) & 255
    int c = (int)((i8 >> 9) & (C_ - 1));
    const float* wc = w + c * 4;
    float w00 = __ldg(wc + 0);
    float w01 = __ldg(wc + 1);
    float w10 = __ldg(wc + 2);
    float w11 = __ldg(wc + 3);

    float a[8], b[8];
    ldg256_nc_cs(xa + off, a);
    ldg256_nc_cs(xb + off, b);

    float ra[8], rb[8];
#pragma unroll
    for (int k = 0; k < 8; k++) {
        ra[k] = fmaf(w00, a[k], w01 * b[k]);
        rb[k] = fmaf(w10, a[k], w11 * b[k]);
    }

    stg256_cs(oa + off, ra);
    stg256_cs(ob + off, rb);
}

extern "C" void kernel_launch(void* const* d_in, const int* in_sizes, int n_in,
                              void* d_out, int out_size)
{
    const float* xa = (const float*)d_in[0];
    const float* xb = (const float*)d_in[1];
    const float* w  = (const float*)d_in[2];

    float* oa = (float*)d_out;
    float* ob = oa + TOT;   // out_b follows out_a

    int threads = 256;
    long long blocks = TOT8 / threads;   // exact: 16384
    cross_stitch_kernel<<<(unsigned)blocks, threads>>>(xa, xb, w, oa, ob);
}

// round 5
// speedup vs baseline: 1.0008x; 1.0008x over previous
#include <cuda_runtime.h>
#include <cuda_bf16.h>
#include <cstdint>

// Cross-stitch: per-channel 2x2 mix.
//   out_a[n,c,h,w] = w[c,0,0]*x_a + w[c,0,1]*x_b
//   out_b[n,c,h,w] = w[c,1,0]*x_a + w[c,1,1]*x_b
// Shapes: x_a, x_b: [32, 256, 64, 64] fp32. weights: [256, 2, 2] fp32.
// Output: out_a followed by out_b.
//
// HBM-bound at the 537MB traffic floor (~6.5TB/s achieved = 82% DRAM).
// 256-bit global accesses, evict-first. This round: 2 chunks per thread with
// all loads front-batched ahead of any store (read-ahead pipelining).

static constexpr int C_ = 256;
static constexpr long long TOT  = 32LL * 256 * 64 * 64;   // 33,554,432 floats
static constexpr long long TOT8 = TOT / 8;                // 4,194,304 float8
static constexpr long long HALF8 = TOT8 / 2;              // 2,097,152 — multiple of
// 256*512 float8s (= 256 channel rows), so i8 and i8+HALF8 share the same channel.

__device__ __forceinline__ void ldg256_cs(const float* __restrict__ p, float r[8]) {
    asm volatile("ld.global.cs.v8.f32 {%0,%1,%2,%3,%4,%5,%6,%7}, [%8];"
                 : "=f"(r[0]), "=f"(r[1]), "=f"(r[2]), "=f"(r[3]),
                   "=f"(r[4]), "=f"(r[5]), "=f"(r[6]), "=f"(r[7])
                 : "l"(p));
}

__device__ __forceinline__ void stg256_cs(float* __restrict__ p, const float r[8]) {
    asm volatile("st.global.cs.v8.f32 [%0], {%1,%2,%3,%4,%5,%6,%7,%8};"
                 :: "l"(p),
                    "f"(r[0]), "f"(r[1]), "f"(r[2]), "f"(r[3]),
                    "f"(r[4]), "f"(r[5]), "f"(r[6]), "f"(r[7])
                 : "memory");
}

__global__ __launch_bounds__(256)
void cross_stitch_kernel(const float* __restrict__ xa,
                         const float* __restrict__ xb,
                         const float* __restrict__ w,   // [C,2,2]
                         float* __restrict__ oa,
                         float* __restrict__ ob)
{
    long long i8 = (long long)blockIdx.x * blockDim.x + threadIdx.x;  // float8 index
    long long off0 = i8 * 8;
    long long off1 = (i8 + HALF8) * 8;

    // channel: float_index / 4096 mod 256 = (i8 >> 9) & 255 (same for both chunks)
    int c = (int)((i8 >> 9) & (C_ - 1));
    const float* wc = w + c * 4;
    float w00 = __ldg(wc + 0);
    float w01 = __ldg(wc + 1);
    float w10 = __ldg(wc + 2);
    float w11 = __ldg(wc + 3);

    // All four 256-bit loads in flight before any compute/store.
    float a0[8], b0[8], a1[8], b1[8];
    ldg256_cs(xa + off0, a0);
    ldg256_cs(xb + off0, b0);
    ldg256_cs(xa + off1, a1);
    ldg256_cs(xb + off1, b1);

    float ra[8], rb[8];
#pragma unroll
    for (int k = 0; k < 8; k++) {
        ra[k] = fmaf(w00, a0[k], w01 * b0[k]);
        rb[k] = fmaf(w10, a0[k], w11 * b0[k]);
    }
    stg256_cs(oa + off0, ra);
    stg256_cs(ob + off0, rb);

#pragma unroll
    for (int k = 0; k < 8; k++) {
        ra[k] = fmaf(w00, a1[k], w01 * b1[k]);
        rb[k] = fmaf(w10, a1[k], w11 * b1[k]);
    }
    stg256_cs(oa + off1, ra);
    stg256_cs(ob + off1, rb);
}

extern "C" void kernel_launch(void* const* d_in, const int* in_sizes, int n_in,
                              void* d_out, int out_size)
{
    const float* xa = (const float*)d_in[0];
    const float* xb = (const float*)d_in[1];
    const float* w  = (const float*)d_in[2];

    float* oa = (float*)d_out;
    float* ob = oa + TOT;   // out_b follows out_a

    int threads = 256;
    long long blocks = HALF8 / threads;   // exact: 8192
    cross_stitch_kernel<<<(unsigned)blocks, threads>>>(xa, xb, w, oa, ob);
}

// round 6
// speedup vs baseline: 1.0035x; 1.0027x over previous
#include <cuda_runtime.h>
#include <cuda_bf16.h>
#include <cstdint>

// Cross-stitch: per-channel 2x2 mix.
//   out_a[n,c,h,w] = w[c,0,0]*x_a + w[c,0,1]*x_b
//   out_b[n,c,h,w] = w[c,1,0]*x_a + w[c,1,1]*x_b
// Shapes: x_a, x_b: [32, 256, 64, 64] fp32. weights: [256, 2, 2] fp32.
// Output: out_a followed by out_b.
//
// ROOFLINE-COMPLETE (5 rounds of evidence): HBM-bound at the 537MB traffic
// floor, ~6.54TB/s achieved (82.6% DRAM). Best config: 256-bit global
// accesses (ld/st.global.v8.f32, sm_100+), evict-first, 1 chunk/thread.
// Probed and rejected: .nc path (neutral), 2-4 chunk batching (neutral to
// -2%), default cache policy (neutral), occupancy (insensitive 48-80%).

static constexpr int C_ = 256;
static constexpr long long TOT  = 32LL * 256 * 64 * 64;   // 33,554,432 floats
static constexpr long long TOT8 = TOT / 8;                // 4,194,304 float8

__device__ __forceinline__ void ldg256_cs(const float* __restrict__ p, float r[8]) {
    asm volatile("ld.global.cs.v8.f32 {%0,%1,%2,%3,%4,%5,%6,%7}, [%8];"
                 : "=f"(r[0]), "=f"(r[1]), "=f"(r[2]), "=f"(r[3]),
                   "=f"(r[4]), "=f"(r[5]), "=f"(r[6]), "=f"(r[7])
                 : "l"(p));
}

__device__ __forceinline__ void stg256_cs(float* __restrict__ p, const float r[8]) {
    asm volatile("st.global.cs.v8.f32 [%0], {%1,%2,%3,%4,%5,%6,%7,%8};"
                 :: "l"(p),
                    "f"(r[0]), "f"(r[1]), "f"(r[2]), "f"(r[3]),
                    "f"(r[4]), "f"(r[5]), "f"(r[6]), "f"(r[7])
                 : "memory");
}

__global__ __launch_bounds__(256)
void cross_stitch_kernel(const float* __restrict__ xa,
                         const float* __restrict__ xb,
                         const float* __restrict__ w,   // [C,2,2]
                         float* __restrict__ oa,
                         float* __restrict__ ob)
{
    long long i8 = (long long)blockIdx.x * blockDim.x + threadIdx.x;  // float8 index
    long long off = i8 * 8;                                           // float offset

    // channel: float_index / 4096 mod 256 = (i8 >> 9) & 255
    int c = (int)((i8 >> 9) & (C_ - 1));
    const float* wc = w + c * 4;
    float w00 = __ldg(wc + 0);
    float w01 = __ldg(wc + 1);
    float w10 = __ldg(wc + 2);
    float w11 = __ldg(wc + 3);

    float a[8], b[8];
    ldg256_cs(xa + off, a);
    ldg256_cs(xb + off, b);

    float ra[8], rb[8];
#pragma unroll
    for (int k = 0; k < 8; k++) {
        ra[k] = fmaf(w00, a[k], w01 * b[k]);
        rb[k] = fmaf(w10, a[k], w11 * b[k]);
    }

    stg256_cs(oa + off, ra);
    stg256_cs(ob + off, rb);
}

extern "C" void kernel_launch(void* const* d_in, const int* in_sizes, int n_in,
                              void* d_out, int out_size)
{
    const float* xa = (const float*)d_in[0];
    const float* xb = (const float*)d_in[1];
    const float* w  = (const float*)d_in[2];

    float* oa = (float*)d_out;
    float* ob = oa + TOT;   // out_b follows out_a

    int threads = 256;
    long long blocks = TOT8 / threads;   // exact: 16384
    cross_stitch_kernel<<<(unsigned)blocks, threads>>>(xa, xb, w, oa, ob);
}

// round 7
// speedup vs baseline: 1.0039x; 1.0004x over previous
#include <cuda_runtime.h>
#include <cuda_bf16.h>
#include <cstdint>

// Cross-stitch: per-channel 2x2 mix.
//   out_a[n,c,h,w] = w[c,0,0]*x_a + w[c,0,1]*x_b
//   out_b[n,c,h,w] = w[c,1,0]*x_a + w[c,1,1]*x_b
// Shapes: x_a, x_b: [32, 256, 64, 64] fp32. weights: [256, 2, 2] fp32.
// Output: out_a followed by out_b.
//
// ROOFLINE-COMPLETE (6 rounds of evidence): HBM-bound at the 537MB traffic
// floor, ~6.5TB/s achieved (81-83% DRAM, run-to-run band ±1.5%). Config:
// 256-bit global accesses (ld/st.global.v8.f32, sm_100+), evict-first,
// 1 chunk/thread. Probed and rejected: .nc path, 2-4 chunk batching,
// default cache policy, occupancy sweep (insensitive 48-80%).
// This round's single variable: 512-thread blocks (predicted neutral).

static constexpr int C_ = 256;
static constexpr long long TOT  = 32LL * 256 * 64 * 64;   // 33,554,432 floats
static constexpr long long TOT8 = TOT / 8;                // 4,194,304 float8

__device__ __forceinline__ void ldg256_cs(const float* __restrict__ p, float r[8]) {
    asm volatile("ld.global.cs.v8.f32 {%0,%1,%2,%3,%4,%5,%6,%7}, [%8];"
                 : "=f"(r[0]), "=f"(r[1]), "=f"(r[2]), "=f"(r[3]),
                   "=f"(r[4]), "=f"(r[5]), "=f"(r[6]), "=f"(r[7])
                 : "l"(p));
}

__device__ __forceinline__ void stg256_cs(float* __restrict__ p, const float r[8]) {
    asm volatile("st.global.cs.v8.f32 [%0], {%1,%2,%3,%4,%5,%6,%7,%8};"
                 :: "l"(p),
                    "f"(r[0]), "f"(r[1]), "f"(r[2]), "f"(r[3]),
                    "f"(r[4]), "f"(r[5]), "f"(r[6]), "f"(r[7])
                 : "memory");
}

__global__ __launch_bounds__(512)
void cross_stitch_kernel(const float* __restrict__ xa,
                         const float* __restrict__ xb,
                         const float* __restrict__ w,   // [C,2,2]
                         float* __restrict__ oa,
                         float* __restrict__ ob)
{
    long long i8 = (long long)blockIdx.x * blockDim.x + threadIdx.x;  // float8 index
    long long off = i8 * 8;                                           // float offset

    // channel: float_index / 4096 mod 256 = (i8 >> 9) & 255
    int c = (int)((i8 >> 9) & (C_ - 1));
    const float* wc = w + c * 4;
    float w00 = __ldg(wc + 0);
    float w01 = __ldg(wc + 1);
    float w10 = __ldg(wc + 2);
    float w11 = __ldg(wc + 3);

    float a[8], b[8];
    ldg256_cs(xa + off, a);
    ldg256_cs(xb + off, b);

    float ra[8], rb[8];
#pragma unroll
    for (int k = 0; k < 8; k++) {
        ra[k] = fmaf(w00, a[k], w01 * b[k]);
        rb[k] = fmaf(w10, a[k], w11 * b[k]);
    }

    stg256_cs(oa + off, ra);
    stg256_cs(ob + off, rb);
}

extern "C" void kernel_launch(void* const* d_in, const int* in_sizes, int n_in,
                              void* d_out, int out_size)
{
    const float* xa = (const float*)d_in[0];
    const float* xb = (const float*)d_in[1];
    const float* w  = (const float*)d_in[2];

    float* oa = (float*)d_out;
    float* ob = oa + TOT;   // out_b follows out_a

    int threads = 512;
    long long blocks = TOT8 / threads;   // exact: 8192
    cross_stitch_kernel<<<(unsigned)blocks, threads>>>(xa, xb, w, oa, ob);
}